// round 13
// baseline (speedup 1.0000x reference)
#include <cuda_runtime.h>
#include <cuda_fp16.h>
#include <math.h>
#include <stdint.h>

#define BATCH 64
#define H 64
#define W 96
#define HW (H * W)
#define UV 81
#define NCH 16

#define BX 64
#define BY 3
#define NTHREADS (BX * BY)

#define L2E       1.4426950408889634f
#define LN2_LN49  0.17811242f
#define LN2_LN81  0.15774409f

// fp16 channel-transposed feat: [b][hw][ch], 16 halves (32B) per pixel
__device__ __half g_featT[(size_t)BATCH * HW * NCH];

__device__ __forceinline__ float ex2(float x) {
    float r; asm("ex2.approx.f32 %0, %1;" : "=f"(r) : "f"(x)); return r;
}
__device__ __forceinline__ float lg2(float x) {
    float r; asm("lg2.approx.f32 %0, %1;" : "=f"(r) : "f"(x)); return r;
}

// ---- kernel 1: feat [b][ch][hw] f32 -> g_featT [b][hw][ch] fp16 ----
__global__ __launch_bounds__(256) void feat_transpose_kernel(
    const float* __restrict__ feat)
{
    __shared__ __half s[NCH][264];
    const int px0 = blockIdx.x * 256;
    const int b   = blockIdx.y;
    const int tid = threadIdx.x;

#pragma unroll
    for (int e = 0; e < 16; e++) {
        int idx = tid + e * 256;            // 0..4095
        int ch  = idx >> 8;
        int px  = idx & 255;
        s[ch][px] = __float2half(__ldg(feat + ((size_t)(b * NCH + ch)) * HW + px0 + px));
    }
    __syncthreads();
#pragma unroll
    for (int e = 0; e < 16; e++) {
        int idx = tid + e * 256;
        int px  = idx >> 4;
        int ch  = idx & 15;
        g_featT[((size_t)b * HW + px0 + px) * NCH + ch] = s[ch][px];
    }
}

__device__ __forceinline__ void h8_to_f(const uint4 q, float2* f) {
    f[0] = __half22float2(*(const __half2*)&q.x);
    f[1] = __half22float2(*(const __half2*)&q.y);
    f[2] = __half22float2(*(const __half2*)&q.z);
    f[3] = __half22float2(*(const __half2*)&q.w);
}

// ---- kernel 2: fused flow_reg + entropy + bilinear warp ----
__global__ __launch_bounds__(NTHREADS, 9) void segnet_flowreg_warp_kernel(
    const float* __restrict__ cost,
    float* __restrict__ out)
{
    __shared__ float s_max[BY][BX];
    __shared__ int   s_am [BY][BX];
    __shared__ float s_part[6][BY][BX];   // Sw, Sx, Sy, Sg, Sgt, Swt

    const int tx = threadIdx.x;
    const int ty = threadIdx.y;

    const int pix = blockIdx.x * BX + tx;
    const int b   = pix / HW;
    const int hw  = pix - b * HW;
    const int h   = hw / W;
    const int w   = hw - h * W;

    // ---- pass 1: load 27 slices (L1-allocating), t = c*log2e,
    //      max/argmax + GLOBAL sums. No t[] array -> low regs. ----
    const float* cp = cost + ((size_t)b * UV + ty * 27) * HW + hw;
    float m = -INFINITY;
    int   amv = ty * 27;
    float Sg = 0.f, Sgt = 0.f;            // sum e, sum e*t  (log2 domain)
#pragma unroll
    for (int j = 0; j < 27; j++) {
        float tv = __ldg(cp + (size_t)j * HW) * L2E;
        if (tv > m) { m = tv; amv = ty * 27 + j; }   // strict >: first occurrence
        float ev = ex2(tv);
        Sg += ev;
        Sgt = fmaf(ev, tv, Sgt);
    }
    s_max[ty][tx] = m;
    s_am [ty][tx] = amv;
    __syncthreads();

    // ---- global max/argmax (ascending q preserves first-occurrence) ----
    float gm  = s_max[0][tx];
    int   gam = s_am [0][tx];
#pragma unroll
    for (int q = 1; q < BY; q++) {
        float v = s_max[q][tx];
        if (v > gm) { gm = v; gam = s_am[q][tx]; }
    }
    const int u0 = gam / 9;
    const int v0 = gam - 9 * u0;

    // ---- v-window masks ----
    float mv[9];
#pragma unroll
    for (int v = 0; v < 9; v++)
        mv[v] = ((unsigned)(v - v0 + 3) <= 6u) ? 1.0f : 0.0f;

    // ---- pass 2: reload (L1-hot) + windowed sums ----
    float Sw = 0.f, Swt = 0.f, Sx = 0.f, Sy = 0.f;
#pragma unroll
    for (int ul = 0; ul < 3; ul++) {
        const int   u  = ty * 3 + ul;
        const float uf = ((unsigned)(u - u0 + 3) <= 6u) ? 1.0f : 0.0f;
        const float du = (float)(u - 4);
        float Rw = 0.f, Rwt = 0.f, Ry = 0.f;
#pragma unroll
        for (int v = 0; v < 9; v++) {
            float tv = __ldg(cp + (size_t)(ul * 9 + v) * HW) * L2E;
            float ew = ex2(tv) * mv[v];
            Rw += ew;
            Rwt = fmaf(ew, tv, Rwt);
            Ry  = fmaf(ew, (float)(v - 4), Ry);
        }
        Sw  = fmaf(uf, Rw,  Sw);
        Swt = fmaf(uf, Rwt, Swt);
        Sy  = fmaf(uf, Ry,  Sy);
        Sx  = fmaf(uf * du, Rw, Sx);
    }
    s_part[0][ty][tx] = Sw;   s_part[1][ty][tx] = Sx;
    s_part[2][ty][tx] = Sy;   s_part[3][ty][tx] = Sg;
    s_part[4][ty][tx] = Sgt;  s_part[5][ty][tx] = Swt;
    __syncthreads();

    // ---- combine (all threads need fx, fy) ----
    float SwT = 0.f, SxT = 0.f, SyT = 0.f;
#pragma unroll
    for (int q = 0; q < BY; q++) {
        SwT += s_part[0][q][tx];
        SxT += s_part[1][q][tx];
        SyT += s_part[2][q][tx];
    }
    const float invSw = 1.0f / SwT;
    const float fx = SxT * invSw;          // flow x = E[u-4]
    const float fy = SyT * invSw;          // flow y = E[v-4]

    float* flow_o = out;
    float* ent_o  = out + (size_t)BATCH * 2 * HW;
    float* warp_o = out + (size_t)BATCH * 4 * HW;

    if (ty == 2) {                         // ty2 writes flow/ent (ty0/1 gather)
        float SgT = 0.f, SgtT = 0.f, SwtT = 0.f;
#pragma unroll
        for (int q = 0; q < BY; q++) {
            SgT  += s_part[3][q][tx];
            SgtT += s_part[4][q][tx];
            SwtT += s_part[5][q][tx];
        }
        // -sum p ln p = ln2 * (lg2 S - (sum e*t)/S)
        const float lent = (lg2(SwT) - SwtT * invSw) * LN2_LN49;
        const float gent = (lg2(SgT) - SgtT / SgT)   * LN2_LN81;
        flow_o[((size_t)b * 2 + 0) * HW + hw] = fx;
        flow_o[((size_t)b * 2 + 1) * HW + hw] = fy;
        ent_o [((size_t)b * 2 + 0) * HW + hw] = lent;
        ent_o [((size_t)b * 2 + 1) * HW + hw] = gent;
    }

    // ---- bilinear backward warp via fp16 transposed feat (8ch per LDG.128) ----
    const float px = (float)w + fx;
    const float py = (float)h + fy;
    const float x0f = floorf(px), y0f = floorf(py);
    const float wx = px - x0f,   wy = py - y0f;
    const int x0 = (int)x0f, y0 = (int)y0f;
    const int x1 = x0 + 1,   y1 = y0 + 1;
    const bool vx0 = (x0 >= 0) & (x0 < W);
    const bool vx1 = (x1 >= 0) & (x1 < W);
    const bool vy0 = (y0 >= 0) & (y0 < H);
    const bool vy1 = (y1 >= 0) & (y1 < H);

    float w00 = (1.f - wx) * (1.f - wy) * ((vx0 & vy0) ? 1.f : 0.f);
    float w01 = wx         * (1.f - wy) * ((vx1 & vy0) ? 1.f : 0.f);
    float w10 = (1.f - wx) * wy         * ((vx0 & vy1) ? 1.f : 0.f);
    float w11 = wx         * wy         * ((vx1 & vy1) ? 1.f : 0.f);

    const float nx = 2.f * px / (float)(W - 1) - 1.f;
    const float ny = 2.f * py / (float)(H - 1) - 1.f;
    const float msk = (fabsf(nx) < 1.f && fabsf(ny) < 1.f) ? 1.f : 0.f;
    w00 *= msk; w01 *= msk; w10 *= msk; w11 *= msk;

    const int x0c = min(max(x0, 0), W - 1), x1c = min(max(x1, 0), W - 1);
    const int y0c = min(max(y0, 0), H - 1), y1c = min(max(y1, 0), H - 1);

    if (ty < 2) {
        const __half* fT = g_featT + (size_t)b * HW * NCH;
        const int g8 = ty * 8;             // channel group: 8 halves = 16B
        const uint4 q00 = *(const uint4*)(fT + (size_t)(y0c * W + x0c) * NCH + g8);
        const uint4 q01 = *(const uint4*)(fT + (size_t)(y0c * W + x1c) * NCH + g8);
        const uint4 q10 = *(const uint4*)(fT + (size_t)(y1c * W + x0c) * NCH + g8);
        const uint4 q11 = *(const uint4*)(fT + (size_t)(y1c * W + x1c) * NCH + g8);
        float2 f00[4], f01[4], f10[4], f11[4];
        h8_to_f(q00, f00); h8_to_f(q01, f01);
        h8_to_f(q10, f10); h8_to_f(q11, f11);
#pragma unroll
        for (int k = 0; k < 4; k++) {
            float vx = w00 * f00[k].x + w01 * f01[k].x + w10 * f10[k].x + w11 * f11[k].x;
            float vy = w00 * f00[k].y + w01 * f01[k].y + w10 * f10[k].y + w11 * f11[k].y;
            __stcs(&warp_o[((size_t)b * NCH + g8 + 2 * k + 0) * HW + hw], vx);
            __stcs(&warp_o[((size_t)b * NCH + g8 + 2 * k + 1) * HW + hw], vy);
        }
    }
}

extern "C" void kernel_launch(void* const* d_in, const int* in_sizes, int n_in,
                              void* d_out, int out_size) {
    const float* cost = (const float*)d_in[0];
    const float* feat = (const float*)d_in[1];
    float* out = (float*)d_out;

    dim3 tgrid(HW / 256, BATCH);               // 24 x 64
    feat_transpose_kernel<<<tgrid, 256>>>(feat);

    dim3 block(BX, BY);                        // 192 threads
    int blocks = BATCH * HW / BX;              // 6144
    segnet_flowreg_warp_kernel<<<blocks, block>>>(cost, out);
}

// round 15
// speedup vs baseline: 1.2934x; 1.2934x over previous
#include <cuda_runtime.h>
#include <cuda_fp16.h>
#include <math.h>
#include <stdint.h>

#define BATCH 64
#define H 64
#define W 96
#define HW (H * W)
#define UV 81
#define NCH 16

#define BX 64
#define BY 3
#define NTHREADS (BX * BY)
#define G 4                   // tiles per CTA, register-pipelined

#define L2E       1.4426950408889634f
#define LN2_LN49  0.17811242f
#define LN2_LN81  0.15774409f

// fp16 channel-transposed feat: [b][hw][ch], 16 halves (32B) per pixel
__device__ __half g_featT[(size_t)BATCH * HW * NCH];

__device__ __forceinline__ float ex2(float x) {
    float r; asm("ex2.approx.f32 %0, %1;" : "=f"(r) : "f"(x)); return r;
}
__device__ __forceinline__ float lg2(float x) {
    float r; asm("lg2.approx.f32 %0, %1;" : "=f"(r) : "f"(x)); return r;
}

// ---- kernel 1: feat [b][ch][hw] f32 -> g_featT [b][hw][ch] fp16 ----
__global__ __launch_bounds__(256) void feat_transpose_kernel(
    const float* __restrict__ feat)
{
    __shared__ __half s[NCH][264];
    const int px0 = blockIdx.x * 256;
    const int b   = blockIdx.y;
    const int tid = threadIdx.x;

#pragma unroll
    for (int e = 0; e < 16; e++) {
        int idx = tid + e * 256;            // 0..4095
        int ch  = idx >> 8;
        int px  = idx & 255;
        s[ch][px] = __float2half(__ldg(feat + ((size_t)(b * NCH + ch)) * HW + px0 + px));
    }
    __syncthreads();
#pragma unroll
    for (int e = 0; e < 16; e++) {
        int idx = tid + e * 256;
        int px  = idx >> 4;
        int ch  = idx & 15;
        g_featT[((size_t)b * HW + px0 + px) * NCH + ch] = s[ch][px];
    }
}

__device__ __forceinline__ void h8_to_f(const uint4 q, float2* f) {
    f[0] = __half22float2(*(const __half2*)&q.x);
    f[1] = __half22float2(*(const __half2*)&q.y);
    f[2] = __half22float2(*(const __half2*)&q.z);
    f[3] = __half22float2(*(const __half2*)&q.w);
}

// ---- kernel 2: fused flow_reg + entropy + bilinear warp, G-tile pipelined ----
__global__ __launch_bounds__(NTHREADS, 4) void segnet_flowreg_warp_kernel(
    const float* __restrict__ cost,
    float* __restrict__ out)
{
    __shared__ float s_max[BY][BX];
    __shared__ int   s_am [BY][BX];
    __shared__ float s_part[6][BY][BX];   // Sw, Sx, Sy, Sg, Sgt, Swt

    const int tx = threadIdx.x;
    const int ty = threadIdx.y;
    const int tile0 = blockIdx.x * G;

    float* flow_o = out;
    float* ent_o  = out + (size_t)BATCH * 2 * HW;
    float* warp_o = out + (size_t)BATCH * 4 * HW;

    float ta[27], tb[27];

    // prefetch loader: 27 raw LDGs into a register array (no consume here)
    auto load27 = [&](float* dst, int tile) {
        const int pix = tile * BX + tx;
        const int bb  = pix / HW;
        const int hww = pix - bb * HW;
        const float* cp = cost + ((size_t)bb * UV + ty * 27) * HW + hww;
#pragma unroll
        for (int j = 0; j < 27; j++)
            dst[j] = __ldcs(cp + (size_t)j * HW);
    };

    // ---- prologue: tile 0 loads in flight ----
    load27(ta, tile0);

#pragma unroll
    for (int g = 0; g < G; g++) {
        float* cur = (g & 1) ? tb : ta;
        float* nxt = (g & 1) ? ta : tb;

        // issue next tile's loads BEFORE consuming current tile (overlap)
        if (g + 1 < G) load27(nxt, tile0 + g + 1);

        const int pix = (tile0 + g) * BX + tx;
        const int b   = pix / HW;
        const int hw  = pix - b * HW;
        const int h   = hw / W;
        const int w   = hw - h * W;

        // ---- pass 1: chunk max/argmax on raw values ----
        float m = -INFINITY;
        int   amv = ty * 27;
#pragma unroll
        for (int j = 0; j < 27; j++) {
            float cv = cur[j];
            if (cv > m) { m = cv; amv = ty * 27 + j; }   // strict >: first occurrence
        }
        s_max[ty][tx] = m;
        s_am [ty][tx] = amv;
        __syncthreads();

        // ---- global max/argmax (ascending q keeps first occurrence) ----
        float gm  = s_max[0][tx];
        int   gam = s_am [0][tx];
#pragma unroll
        for (int q = 1; q < BY; q++) {
            float v = s_max[q][tx];
            if (v > gm) { gm = v; gam = s_am[q][tx]; }
        }
        const int u0 = gam / 9;
        const int v0 = gam - 9 * u0;

        // ---- v-window masks ----
        float mv[9];
#pragma unroll
        for (int v = 0; v < 9; v++)
            mv[v] = ((unsigned)(v - v0 + 3) <= 6u) ? 1.0f : 0.0f;

        // ---- pass 2: single ex2 per value feeds global AND window sums ----
        float Sg = 0.f, Sgt = 0.f;
        float Sw = 0.f, Swt = 0.f, Sx = 0.f, Sy = 0.f;
#pragma unroll
        for (int ul = 0; ul < 3; ul++) {
            const int   u  = ty * 3 + ul;
            const float uf = ((unsigned)(u - u0 + 3) <= 6u) ? 1.0f : 0.0f;
            const float du = (float)(u - 4);
            float Rw = 0.f, Rwt = 0.f, Ry = 0.f;
#pragma unroll
            for (int v = 0; v < 9; v++) {
                float tv = cur[ul * 9 + v] * L2E;     // log2 domain
                float ev = ex2(tv);
                Sg += ev;
                Sgt = fmaf(ev, tv, Sgt);
                float ew = ev * mv[v];
                Rw += ew;
                Rwt = fmaf(ew, tv, Rwt);
                Ry  = fmaf(ew, (float)(v - 4), Ry);
            }
            Sw  = fmaf(uf, Rw,  Sw);
            Swt = fmaf(uf, Rwt, Swt);
            Sy  = fmaf(uf, Ry,  Sy);
            Sx  = fmaf(uf * du, Rw, Sx);
        }
        s_part[0][ty][tx] = Sw;   s_part[1][ty][tx] = Sx;
        s_part[2][ty][tx] = Sy;   s_part[3][ty][tx] = Sg;
        s_part[4][ty][tx] = Sgt;  s_part[5][ty][tx] = Swt;
        __syncthreads();

        // ---- combine (all threads need fx, fy) ----
        float SwT = 0.f, SxT = 0.f, SyT = 0.f;
#pragma unroll
        for (int q = 0; q < BY; q++) {
            SwT += s_part[0][q][tx];
            SxT += s_part[1][q][tx];
            SyT += s_part[2][q][tx];
        }
        const float invSw = 1.0f / SwT;
        const float fx = SxT * invSw;      // flow x = E[u-4]
        const float fy = SyT * invSw;      // flow y = E[v-4]

        if (ty == 2) {                     // ty2 writes flow/ent (ty0/1 gather)
            float SgT = 0.f, SgtT = 0.f, SwtT = 0.f;
#pragma unroll
            for (int q = 0; q < BY; q++) {
                SgT  += s_part[3][q][tx];
                SgtT += s_part[4][q][tx];
                SwtT += s_part[5][q][tx];
            }
            // -sum p ln p = ln2 * (lg2 S - (sum e*t)/S)
            const float lent = (lg2(SwT) - SwtT * invSw) * LN2_LN49;
            const float gent = (lg2(SgT) - SgtT / SgT)   * LN2_LN81;
            flow_o[((size_t)b * 2 + 0) * HW + hw] = fx;
            flow_o[((size_t)b * 2 + 1) * HW + hw] = fy;
            ent_o [((size_t)b * 2 + 0) * HW + hw] = lent;
            ent_o [((size_t)b * 2 + 1) * HW + hw] = gent;
        }

        // ---- bilinear backward warp via fp16 transposed feat ----
        const float px = (float)w + fx;
        const float py = (float)h + fy;
        const float x0f = floorf(px), y0f = floorf(py);
        const float wx = px - x0f,   wy = py - y0f;
        const int x0 = (int)x0f, y0 = (int)y0f;
        const int x1 = x0 + 1,   y1 = y0 + 1;
        const bool vx0 = (x0 >= 0) & (x0 < W);
        const bool vx1 = (x1 >= 0) & (x1 < W);
        const bool vy0 = (y0 >= 0) & (y0 < H);
        const bool vy1 = (y1 >= 0) & (y1 < H);

        float w00 = (1.f - wx) * (1.f - wy) * ((vx0 & vy0) ? 1.f : 0.f);
        float w01 = wx         * (1.f - wy) * ((vx1 & vy0) ? 1.f : 0.f);
        float w10 = (1.f - wx) * wy         * ((vx0 & vy1) ? 1.f : 0.f);
        float w11 = wx         * wy         * ((vx1 & vy1) ? 1.f : 0.f);

        const float nx = 2.f * px / (float)(W - 1) - 1.f;
        const float ny = 2.f * py / (float)(H - 1) - 1.f;
        const float msk = (fabsf(nx) < 1.f && fabsf(ny) < 1.f) ? 1.f : 0.f;
        w00 *= msk; w01 *= msk; w10 *= msk; w11 *= msk;

        const int x0c = min(max(x0, 0), W - 1), x1c = min(max(x1, 0), W - 1);
        const int y0c = min(max(y0, 0), H - 1), y1c = min(max(y1, 0), H - 1);

        if (ty < 2) {
            const __half* fT = g_featT + (size_t)b * HW * NCH;
            const int g8 = ty * 8;         // channel group: 8 halves = 16B
            const uint4 q00 = *(const uint4*)(fT + (size_t)(y0c * W + x0c) * NCH + g8);
            const uint4 q01 = *(const uint4*)(fT + (size_t)(y0c * W + x1c) * NCH + g8);
            const uint4 q10 = *(const uint4*)(fT + (size_t)(y1c * W + x0c) * NCH + g8);
            const uint4 q11 = *(const uint4*)(fT + (size_t)(y1c * W + x1c) * NCH + g8);
            float2 f00[4], f01[4], f10[4], f11[4];
            h8_to_f(q00, f00); h8_to_f(q01, f01);
            h8_to_f(q10, f10); h8_to_f(q11, f11);
#pragma unroll
            for (int k = 0; k < 4; k++) {
                float vx = w00 * f00[k].x + w01 * f01[k].x + w10 * f10[k].x + w11 * f11[k].x;
                float vy = w00 * f00[k].y + w01 * f01[k].y + w10 * f10[k].y + w11 * f11[k].y;
                __stcs(&warp_o[((size_t)b * NCH + g8 + 2 * k + 0) * HW + hw], vx);
                __stcs(&warp_o[((size_t)b * NCH + g8 + 2 * k + 1) * HW + hw], vy);
            }
        }
    }
}

extern "C" void kernel_launch(void* const* d_in, const int* in_sizes, int n_in,
                              void* d_out, int out_size) {
    const float* cost = (const float*)d_in[0];
    const float* feat = (const float*)d_in[1];
    float* out = (float*)d_out;

    dim3 tgrid(HW / 256, BATCH);                // 24 x 64
    feat_transpose_kernel<<<tgrid, 256>>>(feat);

    dim3 block(BX, BY);                         // 192 threads
    int blocks = BATCH * HW / (BX * G);         // 1536
    segnet_flowreg_warp_kernel<<<blocks, block>>>(cost, out);
}

// round 16
// speedup vs baseline: 1.4931x; 1.1543x over previous
#include <cuda_runtime.h>
#include <cuda_fp16.h>
#include <math.h>
#include <stdint.h>

#define BATCH 64
#define H 64
#define W 96
#define HW (H * W)
#define UV 81
#define NCH 16

#define BX 64
#define BY 3
#define NTHREADS (BX * BY)

#define L2E       1.4426950408889634f
#define LN2_LN49  0.17811242f
#define LN2_LN81  0.15774409f

// fp16 channel-transposed feat: [b][hw][ch], 16 halves (32B) per pixel
__device__ __half g_featT[(size_t)BATCH * HW * NCH];

__device__ __forceinline__ float ex2(float x) {
    float r; asm("ex2.approx.f32 %0, %1;" : "=f"(r) : "f"(x)); return r;
}
__device__ __forceinline__ float lg2(float x) {
    float r; asm("lg2.approx.f32 %0, %1;" : "=f"(r) : "f"(x)); return r;
}

// ---- kernel 1: feat [b][ch][hw] f32 -> g_featT [b][hw][ch] fp16 ----
__global__ __launch_bounds__(256) void feat_transpose_kernel(
    const float* __restrict__ feat)
{
    __shared__ __half s[NCH][264];
    const int px0 = blockIdx.x * 256;
    const int b   = blockIdx.y;
    const int tid = threadIdx.x;

#pragma unroll
    for (int e = 0; e < 16; e++) {
        int idx = tid + e * 256;            // 0..4095
        int ch  = idx >> 8;
        int px  = idx & 255;
        s[ch][px] = __float2half(__ldg(feat + ((size_t)(b * NCH + ch)) * HW + px0 + px));
    }
    __syncthreads();
#pragma unroll
    for (int e = 0; e < 16; e++) {
        int idx = tid + e * 256;
        int px  = idx >> 4;
        int ch  = idx & 15;
        g_featT[((size_t)b * HW + px0 + px) * NCH + ch] = s[ch][px];
    }
}

__device__ __forceinline__ void h8_to_f(const uint4 q, float2* f) {
    f[0] = __half22float2(*(const __half2*)&q.x);
    f[1] = __half22float2(*(const __half2*)&q.y);
    f[2] = __half22float2(*(const __half2*)&q.z);
    f[3] = __half22float2(*(const __half2*)&q.w);
}

// ---- kernel 2: fused flow_reg + entropy + bilinear warp ----
__global__ __launch_bounds__(NTHREADS, 8) void segnet_flowreg_warp_kernel(
    const float* __restrict__ cost,
    float* __restrict__ out)
{
    __shared__ float  s_max[BY][BX];
    __shared__ int    s_am [BY][BX];
    __shared__ float4 s_pa[BY][BX];       // (Sw, Sx, Sy, Swt)
    __shared__ float2 s_pb[BY][BX];       // (Sg, Sgt)

    const int tx = threadIdx.x;
    const int ty = threadIdx.y;

    const int pix = blockIdx.x * BX + tx;
    const int b   = pix / HW;
    const int hw  = pix - b * HW;
    const int h   = hw / W;
    const int w   = hw - h * W;

    // ---- pass 1 (lean): load 27 slices, t = c*log2e, chunk max/argmax ----
    const float* cp = cost + ((size_t)b * UV + ty * 27) * HW + hw;
    float t[27];
    float m = -INFINITY;
    int   amv = ty * 27;
#pragma unroll
    for (int j = 0; j < 27; j++) {
        float tv = __ldcs(cp + (size_t)j * HW) * L2E;
        t[j] = tv;
        if (tv > m) { m = tv; amv = ty * 27 + j; }   // strict >: first occurrence
    }
    s_max[ty][tx] = m;
    s_am [ty][tx] = amv;
    __syncthreads();

    // ---- global max/argmax (ascending q preserves first-occurrence) ----
    float gm  = s_max[0][tx];
    int   gam = s_am [0][tx];
#pragma unroll
    for (int q = 1; q < BY; q++) {
        float v = s_max[q][tx];
        if (v > gm) { gm = v; gam = s_am[q][tx]; }
    }
    const int u0 = gam / 9;
    const int v0 = gam - 9 * u0;

    // ---- v-window masks ----
    float mv[9];
#pragma unroll
    for (int v = 0; v < 9; v++)
        mv[v] = ((unsigned)(v - v0 + 3) <= 6u) ? 1.0f : 0.0f;

    // ---- pass 2: single ex2 per value feeds global AND window sums ----
    float Sg = 0.f, Sgt = 0.f;
    float Sw = 0.f, Swt = 0.f, Sx = 0.f, Sy = 0.f;
#pragma unroll
    for (int ul = 0; ul < 3; ul++) {
        const int   u  = ty * 3 + ul;
        const float uf = ((unsigned)(u - u0 + 3) <= 6u) ? 1.0f : 0.0f;
        const float du = (float)(u - 4);
        float Rw = 0.f, Rwt = 0.f, Ry = 0.f;
#pragma unroll
        for (int v = 0; v < 9; v++) {
            float tv = t[ul * 9 + v];
            float ev = ex2(tv);
            Sg += ev;
            Sgt = fmaf(ev, tv, Sgt);
            float ew = ev * mv[v];
            Rw += ew;
            Rwt = fmaf(ew, tv, Rwt);
            Ry  = fmaf(ew, (float)(v - 4), Ry);
        }
        Sw  = fmaf(uf, Rw,  Sw);
        Swt = fmaf(uf, Rwt, Swt);
        Sy  = fmaf(uf, Ry,  Sy);
        Sx  = fmaf(uf * du, Rw, Sx);
    }
    s_pa[ty][tx] = make_float4(Sw, Sx, Sy, Swt);
    s_pb[ty][tx] = make_float2(Sg, Sgt);
    __syncthreads();

    // ---- combine via LDS.128 (all threads need fx, fy) ----
    float4 p0 = s_pa[0][tx], p1 = s_pa[1][tx], p2 = s_pa[2][tx];
    const float SwT  = p0.x + p1.x + p2.x;
    const float SxT  = p0.y + p1.y + p2.y;
    const float SyT  = p0.z + p1.z + p2.z;
    const float invSw = 1.0f / SwT;
    const float fx = SxT * invSw;          // flow x = E[u-4]
    const float fy = SyT * invSw;          // flow y = E[v-4]

    float* flow_o = out;
    float* ent_o  = out + (size_t)BATCH * 2 * HW;
    float* warp_o = out + (size_t)BATCH * 4 * HW;

    if (ty == 2) {                         // flow/ent warps: no gather work
        const float SwtT = p0.w + p1.w + p2.w;
        float2 q0 = s_pb[0][tx], q1 = s_pb[1][tx], q2 = s_pb[2][tx];
        const float SgT  = q0.x + q1.x + q2.x;
        const float SgtT = q0.y + q1.y + q2.y;
        // -sum p ln p = ln2 * (lg2 S - (sum e*t)/S)
        const float lent = (lg2(SwT) - SwtT * invSw) * LN2_LN49;
        const float gent = (lg2(SgT) - SgtT / SgT)   * LN2_LN81;
        flow_o[((size_t)b * 2 + 0) * HW + hw] = fx;
        flow_o[((size_t)b * 2 + 1) * HW + hw] = fy;
        ent_o [((size_t)b * 2 + 0) * HW + hw] = lent;
        ent_o [((size_t)b * 2 + 1) * HW + hw] = gent;
    } else {                               // gather warps: bilinear warp only
        const float px = (float)w + fx;
        const float py = (float)h + fy;
        const float x0f = floorf(px), y0f = floorf(py);
        const float wx = px - x0f,   wy = py - y0f;
        const int x0 = (int)x0f, y0 = (int)y0f;
        const int x1 = x0 + 1,   y1 = y0 + 1;
        const bool vx0 = (x0 >= 0) & (x0 < W);
        const bool vx1 = (x1 >= 0) & (x1 < W);
        const bool vy0 = (y0 >= 0) & (y0 < H);
        const bool vy1 = (y1 >= 0) & (y1 < H);

        float w00 = (1.f - wx) * (1.f - wy) * ((vx0 & vy0) ? 1.f : 0.f);
        float w01 = wx         * (1.f - wy) * ((vx1 & vy0) ? 1.f : 0.f);
        float w10 = (1.f - wx) * wy         * ((vx0 & vy1) ? 1.f : 0.f);
        float w11 = wx         * wy         * ((vx1 & vy1) ? 1.f : 0.f);

        const float nx = 2.f * px / (float)(W - 1) - 1.f;
        const float ny = 2.f * py / (float)(H - 1) - 1.f;
        const float msk = (fabsf(nx) < 1.f && fabsf(ny) < 1.f) ? 1.f : 0.f;
        w00 *= msk; w01 *= msk; w10 *= msk; w11 *= msk;

        const int x0c = min(max(x0, 0), W - 1), x1c = min(max(x1, 0), W - 1);
        const int y0c = min(max(y0, 0), H - 1), y1c = min(max(y1, 0), H - 1);

        const __half* fT = g_featT + (size_t)b * HW * NCH;
        const int g8 = ty * 8;             // channel group: 8 halves = 16B
        const uint4 q00 = *(const uint4*)(fT + (size_t)(y0c * W + x0c) * NCH + g8);
        const uint4 q01 = *(const uint4*)(fT + (size_t)(y0c * W + x1c) * NCH + g8);
        const uint4 q10 = *(const uint4*)(fT + (size_t)(y1c * W + x0c) * NCH + g8);
        const uint4 q11 = *(const uint4*)(fT + (size_t)(y1c * W + x1c) * NCH + g8);
        float2 f00[4], f01[4], f10[4], f11[4];
        h8_to_f(q00, f00); h8_to_f(q01, f01);
        h8_to_f(q10, f10); h8_to_f(q11, f11);
#pragma unroll
        for (int k = 0; k < 4; k++) {
            float vx = w00 * f00[k].x + w01 * f01[k].x + w10 * f10[k].x + w11 * f11[k].x;
            float vy = w00 * f00[k].y + w01 * f01[k].y + w10 * f10[k].y + w11 * f11[k].y;
            __stcs(&warp_o[((size_t)b * NCH + g8 + 2 * k + 0) * HW + hw], vx);
            __stcs(&warp_o[((size_t)b * NCH + g8 + 2 * k + 1) * HW + hw], vy);
        }
    }
}

extern "C" void kernel_launch(void* const* d_in, const int* in_sizes, int n_in,
                              void* d_out, int out_size) {
    const float* cost = (const float*)d_in[0];
    const float* feat = (const float*)d_in[1];
    float* out = (float*)d_out;

    dim3 tgrid(HW / 256, BATCH);               // 24 x 64
    feat_transpose_kernel<<<tgrid, 256>>>(feat);

    dim3 block(BX, BY);                        // 192 threads
    int blocks = BATCH * HW / BX;              // 6144
    segnet_flowreg_warp_kernel<<<blocks, block>>>(cost, out);
}